// round 9
// baseline (speedup 1.0000x reference)
#include <cuda_runtime.h>
#include <cuda_fp16.h>
#include <cstdint>

// ---------------- problem constants ----------------
#define DD   44          // DESIZE
#define HH   48
#define WW   48
#define DHW  (DD*HH*WW)  // 101376 = FLAT
#define NB   4           // batch
#define N1   1024
#define N2   128
#define N3   10
#define NT   216         // 6*6*6 taps
#define NP   108         // tap pairs
#define CONVEY 0.9f

// tile geometry for k_step
#define TX 16
#define TY 16
#define HX 21            // TX + 5
#define HY 21
#define HZ 6
#define HXE 11           // even window positions 0,2,..,20
#define HXO 10           // odd positions 1,3,..,19
#define TILE_ELEMS (HZ*HY*HX)   // 2646
#define NSTEPBLK (3*3*DD)       // 396 blocks, 256 voxels each

// ---------------- device scratch (no allocation allowed) ----------------
__device__ float4 g_neuA[DHW];
__device__ float4 g_neuB[DHW];
__device__ __align__(16) __half2 g_synTh[(size_t)NP * DHW]; // [pair][permvox] fp16 (43.8MB)
__device__ float  g_acc1[NB * N1];
__device__ float  g_acc2[NB * N2];

// ---------------- packed fp32x2 helpers (Blackwell) ----------------
__device__ __forceinline__ unsigned long long pack2(float w) {
    unsigned long long r;
    asm("mov.b64 %0, {%1, %1};" : "=l"(r) : "f"(w));
    return r;
}
__device__ __forceinline__ void ffma2(unsigned long long& acc,
                                      unsigned long long a,
                                      unsigned long long b) {
    asm("fma.rn.f32x2 %0, %1, %2, %0;" : "+l"(acc) : "l"(a), "l"(b));
}
__device__ __forceinline__ unsigned long long add2(unsigned long long a,
                                                   unsigned long long b) {
    unsigned long long r;
    asm("add.rn.f32x2 %0, %1, %2;" : "=l"(r) : "l"(a), "l"(b));
    return r;
}
__device__ __forceinline__ float2 unpack2(unsigned long long v) {
    float2 f;
    asm("mov.b64 {%0, %1}, %2;" : "=f"(f.x), "=f"(f.y) : "l"(v));
    return f;
}

// ---------------- kernel 1: neu = vinput + frame, batch-packed ----------------
__global__ void __launch_bounds__(256) k_init_neu(const float* __restrict__ vin,
                                                  const float* __restrict__ frame) {
    int v = blockIdx.x * 256 + threadIdx.x;
    if (v >= DHW) return;
    float f = frame[v];
    float4 o;
    o.x = vin[0 * DHW + v] + f;
    o.y = vin[1 * DHW + v] + f;
    o.z = vin[2 * DHW + v] + f;
    o.w = vin[3 * DHW + v] + f;
    g_neuA[v] = o;
}

// ---------------- kernel 1b: transpose synapse [vox][tap] -> fp16 [pair][permvox]
__global__ void __launch_bounds__(256) k_transpose(const float* __restrict__ syn) {
    __shared__ float sm[32 * 217];
    const int b  = blockIdx.x;       // 0..3167
    const int sb = b >> 3;           // step block 0..395
    const int w  = b & 7;            // warp-chunk 0..7
    const int bx = sb % 3;
    const int tq = sb / 3;
    const int by = tq % 3;
    const int z  = tq / 3;
    const int x0 = bx * TX, y0 = by * TY;
    const int t  = threadIdx.x;

    const size_t base0 = ((size_t)z * (HH*WW) + (size_t)(y0 + 2*w    ) * WW + x0) * NT;
    const size_t base1 = ((size_t)z * (HH*WW) + (size_t)(y0 + 2*w + 1) * WW + x0) * NT;

#pragma unroll
    for (int i = 0; i < 27; ++i) {          // 27*256 = 6912 = 32*216
        int idx    = i * 256 + t;
        int chunk  = idx / 3456;
        int within = idx - chunk * 3456;
        int vl     = within / NT;            // 0..15
        int tap    = within - vl * NT;
        float val  = syn[(chunk ? base1 : base0) + within];
        sm[(chunk * 16 + vl) * 217 + tap] = val;
    }
    __syncthreads();

    const int lane = t & 31;
    const int prow = t >> 5;                 // 0..7
    const size_t obase = (size_t)sb * 256 + w * 32 + lane;
#pragma unroll
    for (int p = prow; p < NP; p += 8) {
        float w0 = sm[lane * 217 + 2 * p];
        float w1 = sm[lane * 217 + 2 * p + 1];
        g_synTh[(size_t)p * DHW + obase] = __floats2half2_rn(w0, w1);
    }
}

// ---------------- kernel 2: locally-connected step, tap-split + prefetch ring -
__global__ void __launch_bounds__(256) k_step(int dir) {
    __shared__ float4 tileE[HZ * HY * HXE];   // even local-x positions
    __shared__ float4 tileO[HZ * HY * HXO];   // odd  local-x positions

    const int sb = blockIdx.x;               // 0..395
    const int bx = sb % 3;
    const int tq = sb / 3;
    const int by = tq % 3;
    const int z  = tq / 3;
    const int x0 = bx * TX, y0 = by * TY;
    const int t    = threadIdx.x;
    const int lane = t & 31;
    const int warp = t >> 5;
    const int s    = warp * 16 + (lane & 15); // pair slot 0..127
    const int h    = lane >> 4;               // tap hemisphere 0/1
    const int txp  = s & 7;
    const int ty   = s >> 3;

    const float4* __restrict__ src = dir ? g_neuB : g_neuA;
    float4*       __restrict__ dst = dir ? g_neuA : g_neuB;

    // load halo tile (zeros outside the volume)
#pragma unroll
    for (int i = 0; i < 11; ++i) {
        int idx = i * 256 + t;
        if (idx < TILE_ELEMS) {
            int lp = idx % HX;
            int r  = idx / HX;
            int ly = r % HY;
            int lz = r / HY;
            int gx = x0 + lp - 3, gy = y0 + ly - 3, gz = z + lz - 3;
            float4 v = make_float4(0.f, 0.f, 0.f, 0.f);
            if ((unsigned)gx < (unsigned)WW && (unsigned)gy < (unsigned)HH &&
                (unsigned)gz < (unsigned)DD)
                v = src[((size_t)gz * HH + gy) * WW + gx];
            if (lp & 1) tileO[(lz * HY + ly) * HXO + (lp >> 1)] = v;
            else        tileE[(lz * HY + ly) * HXE + (lp >> 1)] = v;
        }
    }
    __syncthreads();

    const int v0 = ty * 16 + 2 * txp;
    const char* wbase = reinterpret_cast<const char*>(g_synTh + ((size_t)sb * 256 + v0));

    const ulonglong2* tE = reinterpret_cast<const ulonglong2*>(tileE);
    const ulonglong2* tO = reinterpret_cast<const ulonglong2*>(tileO);

    unsigned long long a0 = 0ull, a1 = 0ull;  // voxel v0: (b0,b1), (b2,b3)
    unsigned long long c0 = 0ull, c1 = 0ull;  // voxel v0+1

    // weight loader for hemisphere row r (r = dzi*6 + dy, dz = h*3 + dzi)
    auto ldw = [&](int r, uint2& A, uint2& B, uint2& C) {
        const int dz = h * 3 + r / 6;
        const int dy = r % 6;
        const size_t pb = (size_t)(dz * 18 + dy * 3) * DHW;
        A = *reinterpret_cast<const uint2*>(wbase + pb * 4);
        B = *reinterpret_cast<const uint2*>(wbase + (pb + (size_t)DHW) * 4);
        C = *reinterpret_cast<const uint2*>(wbase + (pb + (size_t)(2 * DHW)) * 4);
    };

    uint2 A0, B0, C0, A1, B1, C1;             // depth-2 prefetch ring
    ldw(0, A0, B0, C0);
    ldw(1, A1, B1, C1);

#pragma unroll
    for (int r = 0; r < 18; ++r) {
        // consume current row's weights
        uint2 wA = (r & 1) ? A1 : A0;
        uint2 wB = (r & 1) ? B1 : B0;
        uint2 wC = (r & 1) ? C1 : C0;
        // issue loads for row r+2 into the freed slot BEFORE the compute
        if (r + 2 < 18) {
            if (r & 1) ldw(r + 2, A1, B1, C1);
            else       ldw(r + 2, A0, B0, C0);
        }

        const int dz  = h * 3 + r / 6;
        const int dy  = r % 6;
        const int row = dz * HY + ty + dy;
        const ulonglong2* rE = tE + row * HXE + txp;
        const ulonglong2* rO = tO + row * HXO + txp;
        ulonglong2 n0 = rE[0];   // window pos 2txp+0
        ulonglong2 n1 = rO[0];   // +1
        ulonglong2 n2 = rE[1];   // +2
        ulonglong2 n3 = rO[1];   // +3
        ulonglong2 n4 = rE[2];   // +4
        ulonglong2 n5 = rO[2];   // +5
        ulonglong2 n6 = rE[3];   // +6

#pragma unroll
        for (int q = 0; q < 3; ++q) {
            uint2 u = (q == 0) ? wA : (q == 1) ? wB : wC;
            float2 fa = __half22float2(*reinterpret_cast<__half2*>(&u.x)); // v0: taps 2q,2q+1
            float2 fb = __half22float2(*reinterpret_cast<__half2*>(&u.y)); // v1: taps 2q,2q+1
            unsigned long long wax = pack2(fa.x), way = pack2(fa.y);
            unsigned long long wbx = pack2(fb.x), wby = pack2(fb.y);
            const ulonglong2* m0 = (q == 0) ? &n0 : (q == 1) ? &n2 : &n4; // v0 tap dx=2q
            const ulonglong2* m1 = (q == 0) ? &n1 : (q == 1) ? &n3 : &n5; // shared middle
            const ulonglong2* m2 = (q == 0) ? &n2 : (q == 1) ? &n4 : &n6; // v1 tap dx=2q+1
            ffma2(a0, m0->x, wax); ffma2(a1, m0->y, wax);
            ffma2(a0, m1->x, way); ffma2(a1, m1->y, way);
            ffma2(c0, m1->x, wbx); ffma2(c1, m1->y, wbx);
            ffma2(c0, m2->x, wby); ffma2(c1, m2->y, wby);
        }
    }

    // combine hemispheres within the warp (partner = lane ^ 16)
    a0 = add2(a0, __shfl_xor_sync(0xFFFFFFFFu, a0, 16));
    a1 = add2(a1, __shfl_xor_sync(0xFFFFFFFFu, a1, 16));
    c0 = add2(c0, __shfl_xor_sync(0xFFFFFFFFu, c0, 16));
    c1 = add2(c1, __shfl_xor_sync(0xFFFFFFFFu, c1, 16));

    unsigned long long o0 = h ? c0 : a0;
    unsigned long long o1 = h ? c1 : a1;
    float2 r0 = unpack2(o0), r1 = unpack2(o1);
    float4 o;
    o.x = fmaxf(r0.x, 0.f) * CONVEY;
    o.y = fmaxf(r0.y, 0.f) * CONVEY;
    o.z = fmaxf(r1.x, 0.f) * CONVEY;
    o.w = fmaxf(r1.y, 0.f) * CONVEY;
    size_t obase = ((size_t)z * HH + (y0 + ty)) * WW + (x0 + 2 * txp);
    dst[obase + h] = o;
}

// ---------------- kernel 3: bias-initialize accumulators (every launch!) ------
__global__ void __launch_bounds__(256) k_init_acc(const float* __restrict__ b1,
                                                  const float* __restrict__ b2) {
    int i = blockIdx.x * 256 + threadIdx.x;
    if (i < NB * N1) g_acc1[i] = b1[i & (N1 - 1)];
    if (i < NB * N2) g_acc2[i] = b2[i & (N2 - 1)];
}

// ---------------- kernel 4: FC1 split-K, dual row streams, plain FFMA ---------
#define KSPLIT 576
#define ROWSPB 176   // 576 * 176 == 101376 exactly
#define HALFR  88
__global__ void __launch_bounds__(256) k_gemm1(const float* __restrict__ W1) {
    __shared__ float4 sx[ROWSPB];
    const int f0 = blockIdx.x * ROWSPB;

    if (threadIdx.x < ROWSPB) sx[threadIdx.x] = g_neuB[f0 + threadIdx.x];
    __syncthreads();

    const int j0 = threadIdx.x * 4;
    float a00=0,a01=0,a02=0,a03=0;
    float a10=0,a11=0,a12=0,a13=0;
    float a20=0,a21=0,a22=0,a23=0;
    float a30=0,a31=0,a32=0,a33=0;

    const char* wrow = reinterpret_cast<const char*>(W1) + ((size_t)f0 * N1 + j0) * 4;

#pragma unroll 4
    for (int i = 0; i < HALFR; ++i) {
        // two independent load streams -> 2x outstanding LDG.128
        float4 wA = *reinterpret_cast<const float4*>(wrow + (size_t)i * (N1 * 4));
        float4 wB = *reinterpret_cast<const float4*>(wrow + (size_t)(i + HALFR) * (N1 * 4));
        float4 xA = sx[i];
        float4 xB = sx[i + HALFR];
        a00 += xA.x * wA.x; a01 += xA.x * wA.y; a02 += xA.x * wA.z; a03 += xA.x * wA.w;
        a10 += xA.y * wA.x; a11 += xA.y * wA.y; a12 += xA.y * wA.z; a13 += xA.y * wA.w;
        a20 += xA.z * wA.x; a21 += xA.z * wA.y; a22 += xA.z * wA.z; a23 += xA.z * wA.w;
        a30 += xA.w * wA.x; a31 += xA.w * wA.y; a32 += xA.w * wA.z; a33 += xA.w * wA.w;
        a00 += xB.x * wB.x; a01 += xB.x * wB.y; a02 += xB.x * wB.z; a03 += xB.x * wB.w;
        a10 += xB.y * wB.x; a11 += xB.y * wB.y; a12 += xB.y * wB.z; a13 += xB.y * wB.w;
        a20 += xB.z * wB.x; a21 += xB.z * wB.y; a22 += xB.z * wB.z; a23 += xB.z * wB.w;
        a30 += xB.w * wB.x; a31 += xB.w * wB.y; a32 += xB.w * wB.z; a33 += xB.w * wB.w;
    }

    atomicAdd(&g_acc1[0 * N1 + j0 + 0], a00); atomicAdd(&g_acc1[0 * N1 + j0 + 1], a01);
    atomicAdd(&g_acc1[0 * N1 + j0 + 2], a02); atomicAdd(&g_acc1[0 * N1 + j0 + 3], a03);
    atomicAdd(&g_acc1[1 * N1 + j0 + 0], a10); atomicAdd(&g_acc1[1 * N1 + j0 + 1], a11);
    atomicAdd(&g_acc1[1 * N1 + j0 + 2], a12); atomicAdd(&g_acc1[1 * N1 + j0 + 3], a13);
    atomicAdd(&g_acc1[2 * N1 + j0 + 0], a20); atomicAdd(&g_acc1[2 * N1 + j0 + 1], a21);
    atomicAdd(&g_acc1[2 * N1 + j0 + 2], a22); atomicAdd(&g_acc1[2 * N1 + j0 + 3], a23);
    atomicAdd(&g_acc1[3 * N1 + j0 + 0], a30); atomicAdd(&g_acc1[3 * N1 + j0 + 1], a31);
    atomicAdd(&g_acc1[3 * N1 + j0 + 2], a32); atomicAdd(&g_acc1[3 * N1 + j0 + 3], a33);
}

// ---------------- kernel 5: FC2 (relu(acc1) @ W2), atomics into g_acc2 --------
__global__ void __launch_bounds__(128) k_gemm2(const float* __restrict__ W2) {
    const int t     = threadIdx.x;
    const int jbase = blockIdx.x * 64;
    float acc0 = 0, acc1 = 0, acc2 = 0, acc3 = 0;
#pragma unroll 4
    for (int j = 0; j < 64; ++j) {
        int jj  = jbase + j;
        float w = W2[(size_t)jj * N2 + t];
        acc0 += fmaxf(g_acc1[0 * N1 + jj], 0.f) * w;
        acc1 += fmaxf(g_acc1[1 * N1 + jj], 0.f) * w;
        acc2 += fmaxf(g_acc1[2 * N1 + jj], 0.f) * w;
        acc3 += fmaxf(g_acc1[3 * N1 + jj], 0.f) * w;
    }
    atomicAdd(&g_acc2[0 * N2 + t], acc0);
    atomicAdd(&g_acc2[1 * N2 + t], acc1);
    atomicAdd(&g_acc2[2 * N2 + t], acc2);
    atomicAdd(&g_acc2[3 * N2 + t], acc3);
}

// ---------------- kernel 6: FC3 -> output logits ----------------
__global__ void __launch_bounds__(64) k_fc3(const float* __restrict__ W3,
                                            const float* __restrict__ b3,
                                            float* __restrict__ out) {
    int t = threadIdx.x;
    if (t >= NB * N3) return;
    int b = t / N3, o = t % N3;
    float s = b3[o];
#pragma unroll 8
    for (int k = 0; k < N2; ++k)
        s += fmaxf(g_acc2[b * N2 + k], 0.f) * W3[k * N3 + o];
    out[b * N3 + o] = s;
}

// ---------------- launch ----------------
extern "C" void kernel_launch(void* const* d_in, const int* in_sizes, int n_in,
                              void* d_out, int out_size) {
    const float* vin   = (const float*)d_in[0];
    const float* frame = (const float*)d_in[1];
    const float* syn   = (const float*)d_in[2];
    const float* W1    = (const float*)d_in[3];
    const float* b1    = (const float*)d_in[4];
    const float* W2    = (const float*)d_in[5];
    const float* b2    = (const float*)d_in[6];
    const float* W3    = (const float*)d_in[7];
    const float* b3    = (const float*)d_in[8];
    float* out = (float*)d_out;

    k_init_neu<<<DHW / 256, 256>>>(vin, frame);
    k_transpose<<<NSTEPBLK * 8, 256>>>(syn);

    k_step<<<NSTEPBLK, 256>>>(0);   // A -> B
    k_step<<<NSTEPBLK, 256>>>(1);   // B -> A
    k_step<<<NSTEPBLK, 256>>>(0);   // A -> B
    k_step<<<NSTEPBLK, 256>>>(1);   // B -> A
    k_step<<<NSTEPBLK, 256>>>(0);   // A -> B  (final state in g_neuB)

    k_init_acc<<<18, 256>>>(b1, b2);
    k_gemm1<<<KSPLIT, 256>>>(W1);
    k_gemm2<<<16, 128>>>(W2);
    k_fc3<<<1, 64>>>(W3, b3, out);
}

// round 10
// speedup vs baseline: 1.0681x; 1.0681x over previous
#include <cuda_runtime.h>
#include <cuda_fp16.h>
#include <cstdint>

// ---------------- problem constants ----------------
#define DD   44          // DESIZE
#define HH   48
#define WW   48
#define DHW  (DD*HH*WW)  // 101376 = FLAT
#define NB   4           // batch
#define N1   1024
#define N2   128
#define N3   10
#define NT   216         // 6*6*6 taps
#define NP   108         // tap pairs
#define CONVEY 0.9f

// tile geometry for k_step
#define TX 16
#define TY 16
#define HX 21            // TX + 5
#define HY 21
#define HZ 6
#define HXE 11           // even window positions 0,2,..,20
#define HXO 10           // odd positions 1,3,..,19
#define TILE_ELEMS (HZ*HY*HX)   // 2646
#define NSTEPBLK (3*3*DD)       // 396 blocks, 256 voxels each

// ---------------- device scratch (no allocation allowed) ----------------
__device__ float4 g_neuA[DHW];
__device__ float4 g_neuB[DHW];
__device__ __align__(16) __half2 g_synTh[(size_t)NP * DHW]; // [pair][permvox] fp16 (43.8MB)
__device__ float  g_acc1[NB * N1];
__device__ float  g_acc2[NB * N2];

// ---------------- packed fp32x2 helpers (Blackwell) ----------------
__device__ __forceinline__ unsigned long long pack2(float w) {
    unsigned long long r;
    asm("mov.b64 %0, {%1, %1};" : "=l"(r) : "f"(w));
    return r;
}
__device__ __forceinline__ void ffma2(unsigned long long& acc,
                                      unsigned long long a,
                                      unsigned long long b) {
    asm("fma.rn.f32x2 %0, %1, %2, %0;" : "+l"(acc) : "l"(a), "l"(b));
}
__device__ __forceinline__ unsigned long long add2(unsigned long long a,
                                                   unsigned long long b) {
    unsigned long long r;
    asm("add.rn.f32x2 %0, %1, %2;" : "=l"(r) : "l"(a), "l"(b));
    return r;
}
__device__ __forceinline__ float2 unpack2(unsigned long long v) {
    float2 f;
    asm("mov.b64 {%0, %1}, %2;" : "=f"(f.x), "=f"(f.y) : "l"(v));
    return f;
}

// ---------------- cp.async helpers ----------------
__device__ __forceinline__ void cp_async16(void* smem_dst, const void* gsrc) {
    unsigned saddr = (unsigned)__cvta_generic_to_shared(smem_dst);
    asm volatile("cp.async.cg.shared.global [%0], [%1], 16;" :: "r"(saddr), "l"(gsrc));
}
#define CP_COMMIT() asm volatile("cp.async.commit_group;" ::: "memory")
#define CP_WAIT(n)  asm volatile("cp.async.wait_group %0;" :: "n"(n) : "memory")

// ---------------- kernel 1: neu = vinput + frame, batch-packed ----------------
__global__ void __launch_bounds__(256) k_init_neu(const float* __restrict__ vin,
                                                  const float* __restrict__ frame) {
    int v = blockIdx.x * 256 + threadIdx.x;
    if (v >= DHW) return;
    float f = frame[v];
    float4 o;
    o.x = vin[0 * DHW + v] + f;
    o.y = vin[1 * DHW + v] + f;
    o.z = vin[2 * DHW + v] + f;
    o.w = vin[3 * DHW + v] + f;
    g_neuA[v] = o;
}

// ---------------- kernel 1b: transpose synapse [vox][tap] -> fp16 [pair][permvox]
__global__ void __launch_bounds__(256) k_transpose(const float* __restrict__ syn) {
    __shared__ float sm[32 * 217];
    const int b  = blockIdx.x;       // 0..3167
    const int sb = b >> 3;           // step block 0..395
    const int w  = b & 7;            // warp-chunk 0..7
    const int bx = sb % 3;
    const int tq = sb / 3;
    const int by = tq % 3;
    const int z  = tq / 3;
    const int x0 = bx * TX, y0 = by * TY;
    const int t  = threadIdx.x;

    const size_t base0 = ((size_t)z * (HH*WW) + (size_t)(y0 + 2*w    ) * WW + x0) * NT;
    const size_t base1 = ((size_t)z * (HH*WW) + (size_t)(y0 + 2*w + 1) * WW + x0) * NT;

#pragma unroll
    for (int i = 0; i < 27; ++i) {          // 27*256 = 6912 = 32*216
        int idx    = i * 256 + t;
        int chunk  = idx / 3456;
        int within = idx - chunk * 3456;
        int vl     = within / NT;            // 0..15
        int tap    = within - vl * NT;
        float val  = syn[(chunk ? base1 : base0) + within];
        sm[(chunk * 16 + vl) * 217 + tap] = val;
    }
    __syncthreads();

    const int lane = t & 31;
    const int prow = t >> 5;                 // 0..7
    const size_t obase = (size_t)sb * 256 + w * 32 + lane;
#pragma unroll
    for (int p = prow; p < NP; p += 8) {
        float w0 = sm[lane * 217 + 2 * p];
        float w1 = sm[lane * 217 + 2 * p + 1];
        g_synTh[(size_t)p * DHW + obase] = __floats2half2_rn(w0, w1);
    }
}

// ---------------- kernel 2: locally-connected step, tap-split + prefetch ring -
__global__ void __launch_bounds__(256) k_step(int dir) {
    __shared__ float4 tileE[HZ * HY * HXE];   // even local-x positions
    __shared__ float4 tileO[HZ * HY * HXO];   // odd  local-x positions

    const int sb = blockIdx.x;               // 0..395
    const int bx = sb % 3;
    const int tq = sb / 3;
    const int by = tq % 3;
    const int z  = tq / 3;
    const int x0 = bx * TX, y0 = by * TY;
    const int t    = threadIdx.x;
    const int lane = t & 31;
    const int warp = t >> 5;
    const int s    = warp * 16 + (lane & 15); // pair slot 0..127
    const int h    = lane >> 4;               // tap hemisphere 0/1
    const int txp  = s & 7;
    const int ty   = s >> 3;

    const float4* __restrict__ src = dir ? g_neuB : g_neuA;
    float4*       __restrict__ dst = dir ? g_neuA : g_neuB;

    // load halo tile (zeros outside the volume)
#pragma unroll
    for (int i = 0; i < 11; ++i) {
        int idx = i * 256 + t;
        if (idx < TILE_ELEMS) {
            int lp = idx % HX;
            int r  = idx / HX;
            int ly = r % HY;
            int lz = r / HY;
            int gx = x0 + lp - 3, gy = y0 + ly - 3, gz = z + lz - 3;
            float4 v = make_float4(0.f, 0.f, 0.f, 0.f);
            if ((unsigned)gx < (unsigned)WW && (unsigned)gy < (unsigned)HH &&
                (unsigned)gz < (unsigned)DD)
                v = src[((size_t)gz * HH + gy) * WW + gx];
            if (lp & 1) tileO[(lz * HY + ly) * HXO + (lp >> 1)] = v;
            else        tileE[(lz * HY + ly) * HXE + (lp >> 1)] = v;
        }
    }
    __syncthreads();

    const int v0 = ty * 16 + 2 * txp;
    const char* wbase = reinterpret_cast<const char*>(g_synTh + ((size_t)sb * 256 + v0));

    const ulonglong2* tE = reinterpret_cast<const ulonglong2*>(tileE);
    const ulonglong2* tO = reinterpret_cast<const ulonglong2*>(tileO);

    unsigned long long a0 = 0ull, a1 = 0ull;  // voxel v0: (b0,b1), (b2,b3)
    unsigned long long c0 = 0ull, c1 = 0ull;  // voxel v0+1

    // weight loader for hemisphere row r (r = dzi*6 + dy, dz = h*3 + dzi)
    auto ldw = [&](int r, uint2& A, uint2& B, uint2& C) {
        const int dz = h * 3 + r / 6;
        const int dy = r % 6;
        const size_t pb = (size_t)(dz * 18 + dy * 3) * DHW;
        A = *reinterpret_cast<const uint2*>(wbase + pb * 4);
        B = *reinterpret_cast<const uint2*>(wbase + (pb + (size_t)DHW) * 4);
        C = *reinterpret_cast<const uint2*>(wbase + (pb + (size_t)(2 * DHW)) * 4);
    };

    uint2 A0, B0, C0, A1, B1, C1;             // depth-2 prefetch ring
    ldw(0, A0, B0, C0);
    ldw(1, A1, B1, C1);

#pragma unroll
    for (int r = 0; r < 18; ++r) {
        uint2 wA = (r & 1) ? A1 : A0;
        uint2 wB = (r & 1) ? B1 : B0;
        uint2 wC = (r & 1) ? C1 : C0;
        if (r + 2 < 18) {
            if (r & 1) ldw(r + 2, A1, B1, C1);
            else       ldw(r + 2, A0, B0, C0);
        }

        const int dz  = h * 3 + r / 6;
        const int dy  = r % 6;
        const int row = dz * HY + ty + dy;
        const ulonglong2* rE = tE + row * HXE + txp;
        const ulonglong2* rO = tO + row * HXO + txp;
        ulonglong2 n0 = rE[0];
        ulonglong2 n1 = rO[0];
        ulonglong2 n2 = rE[1];
        ulonglong2 n3 = rO[1];
        ulonglong2 n4 = rE[2];
        ulonglong2 n5 = rO[2];
        ulonglong2 n6 = rE[3];

#pragma unroll
        for (int q = 0; q < 3; ++q) {
            uint2 u = (q == 0) ? wA : (q == 1) ? wB : wC;
            float2 fa = __half22float2(*reinterpret_cast<__half2*>(&u.x));
            float2 fb = __half22float2(*reinterpret_cast<__half2*>(&u.y));
            unsigned long long wax = pack2(fa.x), way = pack2(fa.y);
            unsigned long long wbx = pack2(fb.x), wby = pack2(fb.y);
            const ulonglong2* m0 = (q == 0) ? &n0 : (q == 1) ? &n2 : &n4;
            const ulonglong2* m1 = (q == 0) ? &n1 : (q == 1) ? &n3 : &n5;
            const ulonglong2* m2 = (q == 0) ? &n2 : (q == 1) ? &n4 : &n6;
            ffma2(a0, m0->x, wax); ffma2(a1, m0->y, wax);
            ffma2(a0, m1->x, way); ffma2(a1, m1->y, way);
            ffma2(c0, m1->x, wbx); ffma2(c1, m1->y, wbx);
            ffma2(c0, m2->x, wby); ffma2(c1, m2->y, wby);
        }
    }

    a0 = add2(a0, __shfl_xor_sync(0xFFFFFFFFu, a0, 16));
    a1 = add2(a1, __shfl_xor_sync(0xFFFFFFFFu, a1, 16));
    c0 = add2(c0, __shfl_xor_sync(0xFFFFFFFFu, c0, 16));
    c1 = add2(c1, __shfl_xor_sync(0xFFFFFFFFu, c1, 16));

    unsigned long long o0 = h ? c0 : a0;
    unsigned long long o1 = h ? c1 : a1;
    float2 r0 = unpack2(o0), r1 = unpack2(o1);
    float4 o;
    o.x = fmaxf(r0.x, 0.f) * CONVEY;
    o.y = fmaxf(r0.y, 0.f) * CONVEY;
    o.z = fmaxf(r1.x, 0.f) * CONVEY;
    o.w = fmaxf(r1.y, 0.f) * CONVEY;
    size_t obase = ((size_t)z * HH + (y0 + ty)) * WW + (x0 + 2 * txp);
    dst[obase + h] = o;
}

// ---------------- kernel 3: bias-initialize accumulators (every launch!) ------
__global__ void __launch_bounds__(256) k_init_acc(const float* __restrict__ b1,
                                                  const float* __restrict__ b2) {
    int i = blockIdx.x * 256 + threadIdx.x;
    if (i < NB * N1) g_acc1[i] = b1[i & (N1 - 1)];
    if (i < NB * N2) g_acc2[i] = b2[i & (N2 - 1)];
}

// ---------------- kernel 4: FC1 split-K via cp.async deep pipeline ------------
// Each thread owns a fixed 16B (4 cols) slice of each 4KB W1 row; rows stream
// through an 8-stage smem ring with per-thread produce/consume (no block sync
// in the main loop). 7 rows in flight per thread -> DRAM stays saturated even
// with latency inflation.
#define KSPLIT  576
#define ROWSPB  176   // 576 * 176 == 101376 exactly
#define GSTAGES 8
__global__ void __launch_bounds__(256) k_gemm1(const float* __restrict__ W1) {
    __shared__ float4 swb[GSTAGES][256];   // 32KB ring
    __shared__ float4 sx[ROWSPB];
    const int f0  = blockIdx.x * ROWSPB;
    const int tid = threadIdx.x;

    if (tid < ROWSPB) sx[tid] = g_neuB[f0 + tid];

    const char* gbase = reinterpret_cast<const char*>(W1)
                      + ((size_t)f0 * N1 + tid * 4) * 4;

    // prologue: stages 0..6 in flight
#pragma unroll
    for (int s = 0; s < GSTAGES - 1; ++s) {
        cp_async16(&swb[s][tid], gbase + (size_t)s * (N1 * 4));
        CP_COMMIT();
    }
    __syncthreads();   // sx visibility

    const int j0 = tid * 4;
    float a00=0,a01=0,a02=0,a03=0;
    float a10=0,a11=0,a12=0,a13=0;
    float a20=0,a21=0,a22=0,a23=0;
    float a30=0,a31=0,a32=0,a33=0;

#pragma unroll 8
    for (int i = 0; i < ROWSPB; ++i) {
        CP_WAIT(GSTAGES - 2);                 // row i ready (own 16B slot)
        float4 w  = swb[i & (GSTAGES - 1)][tid];
        float4 xv = sx[i];
        a00 += xv.x * w.x; a01 += xv.x * w.y; a02 += xv.x * w.z; a03 += xv.x * w.w;
        a10 += xv.y * w.x; a11 += xv.y * w.y; a12 += xv.y * w.z; a13 += xv.y * w.w;
        a20 += xv.z * w.x; a21 += xv.z * w.y; a22 += xv.z * w.z; a23 += xv.z * w.w;
        a30 += xv.w * w.x; a31 += xv.w * w.y; a32 += xv.w * w.z; a33 += xv.w * w.w;
        if (i + GSTAGES - 1 < ROWSPB)
            cp_async16(&swb[(i + GSTAGES - 1) & (GSTAGES - 1)][tid],
                       gbase + (size_t)(i + GSTAGES - 1) * (N1 * 4));
        CP_COMMIT();                          // keep group counting aligned
    }

    atomicAdd(&g_acc1[0 * N1 + j0 + 0], a00); atomicAdd(&g_acc1[0 * N1 + j0 + 1], a01);
    atomicAdd(&g_acc1[0 * N1 + j0 + 2], a02); atomicAdd(&g_acc1[0 * N1 + j0 + 3], a03);
    atomicAdd(&g_acc1[1 * N1 + j0 + 0], a10); atomicAdd(&g_acc1[1 * N1 + j0 + 1], a11);
    atomicAdd(&g_acc1[1 * N1 + j0 + 2], a12); atomicAdd(&g_acc1[1 * N1 + j0 + 3], a13);
    atomicAdd(&g_acc1[2 * N1 + j0 + 0], a20); atomicAdd(&g_acc1[2 * N1 + j0 + 1], a21);
    atomicAdd(&g_acc1[2 * N1 + j0 + 2], a22); atomicAdd(&g_acc1[2 * N1 + j0 + 3], a23);
    atomicAdd(&g_acc1[3 * N1 + j0 + 0], a30); atomicAdd(&g_acc1[3 * N1 + j0 + 1], a31);
    atomicAdd(&g_acc1[3 * N1 + j0 + 2], a32); atomicAdd(&g_acc1[3 * N1 + j0 + 3], a33);
}

// ---------------- kernel 5: FC2 (relu(acc1) @ W2), atomics into g_acc2 --------
__global__ void __launch_bounds__(128) k_gemm2(const float* __restrict__ W2) {
    const int t     = threadIdx.x;
    const int jbase = blockIdx.x * 64;
    float acc0 = 0, acc1 = 0, acc2 = 0, acc3 = 0;
#pragma unroll 4
    for (int j = 0; j < 64; ++j) {
        int jj  = jbase + j;
        float w = W2[(size_t)jj * N2 + t];
        acc0 += fmaxf(g_acc1[0 * N1 + jj], 0.f) * w;
        acc1 += fmaxf(g_acc1[1 * N1 + jj], 0.f) * w;
        acc2 += fmaxf(g_acc1[2 * N1 + jj], 0.f) * w;
        acc3 += fmaxf(g_acc1[3 * N1 + jj], 0.f) * w;
    }
    atomicAdd(&g_acc2[0 * N2 + t], acc0);
    atomicAdd(&g_acc2[1 * N2 + t], acc1);
    atomicAdd(&g_acc2[2 * N2 + t], acc2);
    atomicAdd(&g_acc2[3 * N2 + t], acc3);
}

// ---------------- kernel 6: FC3 -> output logits ----------------
__global__ void __launch_bounds__(64) k_fc3(const float* __restrict__ W3,
                                            const float* __restrict__ b3,
                                            float* __restrict__ out) {
    int t = threadIdx.x;
    if (t >= NB * N3) return;
    int b = t / N3, o = t % N3;
    float s = b3[o];
#pragma unroll 8
    for (int k = 0; k < N2; ++k)
        s += fmaxf(g_acc2[b * N2 + k], 0.f) * W3[k * N3 + o];
    out[b * N3 + o] = s;
}

// ---------------- launch ----------------
extern "C" void kernel_launch(void* const* d_in, const int* in_sizes, int n_in,
                              void* d_out, int out_size) {
    const float* vin   = (const float*)d_in[0];
    const float* frame = (const float*)d_in[1];
    const float* syn   = (const float*)d_in[2];
    const float* W1    = (const float*)d_in[3];
    const float* b1    = (const float*)d_in[4];
    const float* W2    = (const float*)d_in[5];
    const float* b2    = (const float*)d_in[6];
    const float* W3    = (const float*)d_in[7];
    const float* b3    = (const float*)d_in[8];
    float* out = (float*)d_out;

    k_init_neu<<<DHW / 256, 256>>>(vin, frame);
    k_transpose<<<NSTEPBLK * 8, 256>>>(syn);

    k_step<<<NSTEPBLK, 256>>>(0);   // A -> B
    k_step<<<NSTEPBLK, 256>>>(1);   // B -> A
    k_step<<<NSTEPBLK, 256>>>(0);   // A -> B
    k_step<<<NSTEPBLK, 256>>>(1);   // B -> A
    k_step<<<NSTEPBLK, 256>>>(0);   // A -> B  (final state in g_neuB)

    k_init_acc<<<18, 256>>>(b1, b2);
    k_gemm1<<<KSPLIT, 256>>>(W1);
    k_gemm2<<<16, 128>>>(W2);
    k_fc3<<<1, 64>>>(W3, b3, out);
}

// round 11
// speedup vs baseline: 1.0849x; 1.0157x over previous
#include <cuda_runtime.h>
#include <cuda_fp16.h>
#include <cstdint>

// ---------------- problem constants ----------------
#define DD   44          // DESIZE
#define HH   48
#define WW   48
#define DHW  (DD*HH*WW)  // 101376 = FLAT
#define NB   4           // batch
#define N1   1024
#define N2   128
#define N3   10
#define NT   216         // 6*6*6 taps
#define NP   108         // tap pairs
#define CONVEY 0.9f

// tile geometry for k_step
#define TX 16
#define TY 16
#define HX 21            // TX + 5
#define HY 21
#define HZ 6
#define HXE 11           // even window positions 0,2,..,20
#define HXO 10           // odd positions 1,3,..,19
#define TILE_ELEMS (HZ*HY*HX)   // 2646
#define NSTEPBLK (3*3*DD)       // 396 blocks, 256 voxels each

// ---------------- device scratch (no allocation allowed) ----------------
__device__ float4 g_neuA[DHW];
__device__ float4 g_neuB[DHW];
__device__ __align__(16) __half2 g_synTh[(size_t)NP * DHW]; // [pair][permvox] fp16 (43.8MB)
__device__ float  g_acc1[NB * N1];
__device__ float  g_acc2[NB * N2];

// ---------------- packed fp32x2 helpers (Blackwell) ----------------
__device__ __forceinline__ unsigned long long pack2(float w) {
    unsigned long long r;
    asm("mov.b64 %0, {%1, %1};" : "=l"(r) : "f"(w));
    return r;
}
__device__ __forceinline__ void ffma2(unsigned long long& acc,
                                      unsigned long long a,
                                      unsigned long long b) {
    asm("fma.rn.f32x2 %0, %1, %2, %0;" : "+l"(acc) : "l"(a), "l"(b));
}
__device__ __forceinline__ unsigned long long add2(unsigned long long a,
                                                   unsigned long long b) {
    unsigned long long r;
    asm("add.rn.f32x2 %0, %1, %2;" : "=l"(r) : "l"(a), "l"(b));
    return r;
}
__device__ __forceinline__ float2 unpack2(unsigned long long v) {
    float2 f;
    asm("mov.b64 {%0, %1}, %2;" : "=f"(f.x), "=f"(f.y) : "l"(v));
    return f;
}

// ---------------- cp.async helpers ----------------
__device__ __forceinline__ void cp_async16(void* smem_dst, const void* gsrc) {
    unsigned saddr = (unsigned)__cvta_generic_to_shared(smem_dst);
    asm volatile("cp.async.cg.shared.global [%0], [%1], 16;" :: "r"(saddr), "l"(gsrc));
}
#define CP_COMMIT() asm volatile("cp.async.commit_group;" ::: "memory")
#define CP_WAIT(n)  asm volatile("cp.async.wait_group %0;" :: "n"(n) : "memory")

// ---------------- kernel 1: neu = vinput + frame, batch-packed ----------------
__global__ void __launch_bounds__(256) k_init_neu(const float* __restrict__ vin,
                                                  const float* __restrict__ frame) {
    int v = blockIdx.x * 256 + threadIdx.x;
    if (v >= DHW) return;
    float f = frame[v];
    float4 o;
    o.x = vin[0 * DHW + v] + f;
    o.y = vin[1 * DHW + v] + f;
    o.z = vin[2 * DHW + v] + f;
    o.w = vin[3 * DHW + v] + f;
    g_neuA[v] = o;
}

// ---------------- kernel 1b: transpose synapse [vox][tap] -> fp16 [pair][permvox]
__global__ void __launch_bounds__(256) k_transpose(const float* __restrict__ syn) {
    __shared__ float sm[32 * 217];
    const int b  = blockIdx.x;       // 0..3167
    const int sb = b >> 3;           // step block 0..395
    const int w  = b & 7;            // warp-chunk 0..7
    const int bx = sb % 3;
    const int tq = sb / 3;
    const int by = tq % 3;
    const int z  = tq / 3;
    const int x0 = bx * TX, y0 = by * TY;
    const int t  = threadIdx.x;

    const size_t base0 = ((size_t)z * (HH*WW) + (size_t)(y0 + 2*w    ) * WW + x0) * NT;
    const size_t base1 = ((size_t)z * (HH*WW) + (size_t)(y0 + 2*w + 1) * WW + x0) * NT;

#pragma unroll
    for (int i = 0; i < 27; ++i) {          // 27*256 = 6912 = 32*216
        int idx    = i * 256 + t;
        int chunk  = idx / 3456;
        int within = idx - chunk * 3456;
        int vl     = within / NT;            // 0..15
        int tap    = within - vl * NT;
        float val  = syn[(chunk ? base1 : base0) + within];
        sm[(chunk * 16 + vl) * 217 + tap] = val;
    }
    __syncthreads();

    const int lane = t & 31;
    const int prow = t >> 5;                 // 0..7
    const size_t obase = (size_t)sb * 256 + w * 32 + lane;
#pragma unroll
    for (int p = prow; p < NP; p += 8) {
        float w0 = sm[lane * 217 + 2 * p];
        float w1 = sm[lane * 217 + 2 * p + 1];
        g_synTh[(size_t)p * DHW + obase] = __floats2half2_rn(w0, w1);
    }
}

// ---------------- kernel 2: locally-connected step, tap-split, deep weight ring
__global__ void __launch_bounds__(256) k_step(int dir) {
    __shared__ float4 tileE[HZ * HY * HXE];   // even local-x positions
    __shared__ float4 tileO[HZ * HY * HXO];   // odd  local-x positions

    const int sb = blockIdx.x;               // 0..395
    const int bx = sb % 3;
    const int tq = sb / 3;
    const int by = tq % 3;
    const int z  = tq / 3;
    const int x0 = bx * TX, y0 = by * TY;
    const int t    = threadIdx.x;
    const int lane = t & 31;
    const int warp = t >> 5;
    const int s    = warp * 16 + (lane & 15); // pair slot 0..127
    const int h    = lane >> 4;               // tap hemisphere 0/1
    const int txp  = s & 7;
    const int ty   = s >> 3;

    const float4* __restrict__ src = dir ? g_neuB : g_neuA;
    float4*       __restrict__ dst = dir ? g_neuA : g_neuB;

    // load halo tile (zeros outside the volume)
#pragma unroll
    for (int i = 0; i < 11; ++i) {
        int idx = i * 256 + t;
        if (idx < TILE_ELEMS) {
            int lp = idx % HX;
            int r  = idx / HX;
            int ly = r % HY;
            int lz = r / HY;
            int gx = x0 + lp - 3, gy = y0 + ly - 3, gz = z + lz - 3;
            float4 v = make_float4(0.f, 0.f, 0.f, 0.f);
            if ((unsigned)gx < (unsigned)WW && (unsigned)gy < (unsigned)HH &&
                (unsigned)gz < (unsigned)DD)
                v = src[((size_t)gz * HH + gy) * WW + gx];
            if (lp & 1) tileO[(lz * HY + ly) * HXO + (lp >> 1)] = v;
            else        tileE[(lz * HY + ly) * HXE + (lp >> 1)] = v;
        }
    }
    __syncthreads();

    const int v0 = ty * 16 + 2 * txp;
    const char* wbase = reinterpret_cast<const char*>(g_synTh + ((size_t)sb * 256 + v0));

    const ulonglong2* tE = reinterpret_cast<const ulonglong2*>(tileE);
    const ulonglong2* tO = reinterpret_cast<const ulonglong2*>(tileO);

    unsigned long long a0 = 0ull, a1 = 0ull;  // voxel v0: (b0,b1), (b2,b3)
    unsigned long long c0 = 0ull, c1 = 0ull;  // voxel v0+1

    // weight loader for hemisphere row r (r = dzi*6 + dy, dz = h*3 + dzi)
    auto ldw = [&](int r, uint2& A, uint2& B, uint2& C) {
        const int dz = h * 3 + r / 6;
        const int dy = r % 6;
        const size_t pb = (size_t)(dz * 18 + dy * 3) * DHW;
        A = *reinterpret_cast<const uint2*>(wbase + pb * 4);
        B = *reinterpret_cast<const uint2*>(wbase + (pb + (size_t)DHW) * 4);
        C = *reinterpret_cast<const uint2*>(wbase + (pb + (size_t)(2 * DHW)) * 4);
    };

    // depth-6 row prefetch ring (18 uint2 in registers)
    uint2 WA[6], WB[6], WC[6];
#pragma unroll
    for (int r = 0; r < 6; ++r) ldw(r, WA[r], WB[r], WC[r]);

#pragma unroll
    for (int r = 0; r < 18; ++r) {
        const int sl = r % 6;                 // compile-time after full unroll
        uint2 wA = WA[sl];
        uint2 wB = WB[sl];
        uint2 wC = WC[sl];
        if (r + 6 < 18) ldw(r + 6, WA[sl], WB[sl], WC[sl]);

        const int dz  = h * 3 + r / 6;
        const int dy  = r % 6;
        const int row = dz * HY + ty + dy;
        const ulonglong2* rE = tE + row * HXE + txp;
        const ulonglong2* rO = tO + row * HXO + txp;
        ulonglong2 n0 = rE[0];
        ulonglong2 n1 = rO[0];
        ulonglong2 n2 = rE[1];
        ulonglong2 n3 = rO[1];
        ulonglong2 n4 = rE[2];
        ulonglong2 n5 = rO[2];
        ulonglong2 n6 = rE[3];

#pragma unroll
        for (int q = 0; q < 3; ++q) {
            uint2 u = (q == 0) ? wA : (q == 1) ? wB : wC;
            float2 fa = __half22float2(*reinterpret_cast<__half2*>(&u.x));
            float2 fb = __half22float2(*reinterpret_cast<__half2*>(&u.y));
            unsigned long long wax = pack2(fa.x), way = pack2(fa.y);
            unsigned long long wbx = pack2(fb.x), wby = pack2(fb.y);
            const ulonglong2* m0 = (q == 0) ? &n0 : (q == 1) ? &n2 : &n4;
            const ulonglong2* m1 = (q == 0) ? &n1 : (q == 1) ? &n3 : &n5;
            const ulonglong2* m2 = (q == 0) ? &n2 : (q == 1) ? &n4 : &n6;
            ffma2(a0, m0->x, wax); ffma2(a1, m0->y, wax);
            ffma2(a0, m1->x, way); ffma2(a1, m1->y, way);
            ffma2(c0, m1->x, wbx); ffma2(c1, m1->y, wbx);
            ffma2(c0, m2->x, wby); ffma2(c1, m2->y, wby);
        }
    }

    a0 = add2(a0, __shfl_xor_sync(0xFFFFFFFFu, a0, 16));
    a1 = add2(a1, __shfl_xor_sync(0xFFFFFFFFu, a1, 16));
    c0 = add2(c0, __shfl_xor_sync(0xFFFFFFFFu, c0, 16));
    c1 = add2(c1, __shfl_xor_sync(0xFFFFFFFFu, c1, 16));

    unsigned long long o0 = h ? c0 : a0;
    unsigned long long o1 = h ? c1 : a1;
    float2 r0 = unpack2(o0), r1 = unpack2(o1);
    float4 o;
    o.x = fmaxf(r0.x, 0.f) * CONVEY;
    o.y = fmaxf(r0.y, 0.f) * CONVEY;
    o.z = fmaxf(r1.x, 0.f) * CONVEY;
    o.w = fmaxf(r1.y, 0.f) * CONVEY;
    size_t obase = ((size_t)z * HH + (y0 + ty)) * WW + (x0 + 2 * txp);
    dst[obase + h] = o;
}

// ---------------- kernel 3: bias-initialize accumulators (every launch!) ------
__global__ void __launch_bounds__(256) k_init_acc(const float* __restrict__ b1,
                                                  const float* __restrict__ b2) {
    int i = blockIdx.x * 256 + threadIdx.x;
    if (i < NB * N1) g_acc1[i] = b1[i & (N1 - 1)];
    if (i < NB * N2) g_acc2[i] = b2[i & (N2 - 1)];
}

// ---------------- kernel 4: FC1 split-K via cp.async deep pipeline ------------
#define KSPLIT  576
#define ROWSPB  176   // 576 * 176 == 101376 exactly
#define GSTAGES 12
__global__ void __launch_bounds__(256) k_gemm1(const float* __restrict__ W1) {
    __shared__ float4 swb[GSTAGES][256];   // 48KB ring
    __shared__ float4 sx[ROWSPB];
    const int f0  = blockIdx.x * ROWSPB;
    const int tid = threadIdx.x;

    if (tid < ROWSPB) sx[tid] = g_neuB[f0 + tid];

    const char* gbase = reinterpret_cast<const char*>(W1)
                      + ((size_t)f0 * N1 + tid * 4) * 4;

    // prologue: stages 0..10 in flight
#pragma unroll
    for (int s = 0; s < GSTAGES - 1; ++s) {
        cp_async16(&swb[s][tid], gbase + (size_t)s * (N1 * 4));
        CP_COMMIT();
    }
    __syncthreads();   // sx visibility

    const int j0 = tid * 4;
    float a00=0,a01=0,a02=0,a03=0;
    float a10=0,a11=0,a12=0,a13=0;
    float a20=0,a21=0,a22=0,a23=0;
    float a30=0,a31=0,a32=0,a33=0;

#pragma unroll 12
    for (int i = 0; i < ROWSPB; ++i) {
        CP_WAIT(GSTAGES - 2);                 // row i ready (own 16B slot)
        float4 w  = swb[i % GSTAGES][tid];
        float4 xv = sx[i];
        a00 += xv.x * w.x; a01 += xv.x * w.y; a02 += xv.x * w.z; a03 += xv.x * w.w;
        a10 += xv.y * w.x; a11 += xv.y * w.y; a12 += xv.y * w.z; a13 += xv.y * w.w;
        a20 += xv.z * w.x; a21 += xv.z * w.y; a22 += xv.z * w.z; a23 += xv.z * w.w;
        a30 += xv.w * w.x; a31 += xv.w * w.y; a32 += xv.w * w.z; a33 += xv.w * w.w;
        if (i + GSTAGES - 1 < ROWSPB)
            cp_async16(&swb[(i + GSTAGES - 1) % GSTAGES][tid],
                       gbase + (size_t)(i + GSTAGES - 1) * (N1 * 4));
        CP_COMMIT();                          // keep group counting aligned
    }

    atomicAdd(&g_acc1[0 * N1 + j0 + 0], a00); atomicAdd(&g_acc1[0 * N1 + j0 + 1], a01);
    atomicAdd(&g_acc1[0 * N1 + j0 + 2], a02); atomicAdd(&g_acc1[0 * N1 + j0 + 3], a03);
    atomicAdd(&g_acc1[1 * N1 + j0 + 0], a10); atomicAdd(&g_acc1[1 * N1 + j0 + 1], a11);
    atomicAdd(&g_acc1[1 * N1 + j0 + 2], a12); atomicAdd(&g_acc1[1 * N1 + j0 + 3], a13);
    atomicAdd(&g_acc1[2 * N1 + j0 + 0], a20); atomicAdd(&g_acc1[2 * N1 + j0 + 1], a21);
    atomicAdd(&g_acc1[2 * N1 + j0 + 2], a22); atomicAdd(&g_acc1[2 * N1 + j0 + 3], a23);
    atomicAdd(&g_acc1[3 * N1 + j0 + 0], a30); atomicAdd(&g_acc1[3 * N1 + j0 + 1], a31);
    atomicAdd(&g_acc1[3 * N1 + j0 + 2], a32); atomicAdd(&g_acc1[3 * N1 + j0 + 3], a33);
}

// ---------------- kernel 5: FC2 (relu(acc1) @ W2), atomics into g_acc2 --------
__global__ void __launch_bounds__(128) k_gemm2(const float* __restrict__ W2) {
    const int t     = threadIdx.x;
    const int jbase = blockIdx.x * 64;
    float acc0 = 0, acc1 = 0, acc2 = 0, acc3 = 0;
#pragma unroll 4
    for (int j = 0; j < 64; ++j) {
        int jj  = jbase + j;
        float w = W2[(size_t)jj * N2 + t];
        acc0 += fmaxf(g_acc1[0 * N1 + jj], 0.f) * w;
        acc1 += fmaxf(g_acc1[1 * N1 + jj], 0.f) * w;
        acc2 += fmaxf(g_acc1[2 * N1 + jj], 0.f) * w;
        acc3 += fmaxf(g_acc1[3 * N1 + jj], 0.f) * w;
    }
    atomicAdd(&g_acc2[0 * N2 + t], acc0);
    atomicAdd(&g_acc2[1 * N2 + t], acc1);
    atomicAdd(&g_acc2[2 * N2 + t], acc2);
    atomicAdd(&g_acc2[3 * N2 + t], acc3);
}

// ---------------- kernel 6: FC3 -> output logits ----------------
__global__ void __launch_bounds__(64) k_fc3(const float* __restrict__ W3,
                                            const float* __restrict__ b3,
                                            float* __restrict__ out) {
    int t = threadIdx.x;
    if (t >= NB * N3) return;
    int b = t / N3, o = t % N3;
    float s = b3[o];
#pragma unroll 8
    for (int k = 0; k < N2; ++k)
        s += fmaxf(g_acc2[b * N2 + k], 0.f) * W3[k * N3 + o];
    out[b * N3 + o] = s;
}

// ---------------- launch ----------------
extern "C" void kernel_launch(void* const* d_in, const int* in_sizes, int n_in,
                              void* d_out, int out_size) {
    const float* vin   = (const float*)d_in[0];
    const float* frame = (const float*)d_in[1];
    const float* syn   = (const float*)d_in[2];
    const float* W1    = (const float*)d_in[3];
    const float* b1    = (const float*)d_in[4];
    const float* W2    = (const float*)d_in[5];
    const float* b2    = (const float*)d_in[6];
    const float* W3    = (const float*)d_in[7];
    const float* b3    = (const float*)d_in[8];
    float* out = (float*)d_out;

    k_init_neu<<<DHW / 256, 256>>>(vin, frame);
    k_transpose<<<NSTEPBLK * 8, 256>>>(syn);

    k_step<<<NSTEPBLK, 256>>>(0);   // A -> B
    k_step<<<NSTEPBLK, 256>>>(1);   // B -> A
    k_step<<<NSTEPBLK, 256>>>(0);   // A -> B
    k_step<<<NSTEPBLK, 256>>>(1);   // B -> A
    k_step<<<NSTEPBLK, 256>>>(0);   // A -> B  (final state in g_neuB)

    k_init_acc<<<18, 256>>>(b1, b2);
    k_gemm1<<<KSPLIT, 256>>>(W1);
    k_gemm2<<<16, 128>>>(W2);
    k_fc3<<<1, 64>>>(W3, b3, out);
}